// round 7
// baseline (speedup 1.0000x reference)
#include <cuda_runtime.h>
#include <cuda_fp16.h>
#include <cstdint>

#define NV 100000
#define TT 128
#define NE 1600000
#define KK 9
#define NT (NV * TT)
#define SCAN_B 1024
#define NBLK_SCAN ((NV + SCAN_B - 1) / SCAN_B)   // 98
#define RED_CHUNK 16384

// ---------------- scratch (static __device__, no allocation) ----------------
__device__ int    g_deg[NV];
__device__ float  g_inv[NV];
__device__ int    g_rowptr[NV + 1];
__device__ int    g_cursor[NV];
__device__ int    g_col[NE];
__device__ int    g_bsum[NBLK_SCAN];
__device__ __half g_HA[NT];
__device__ __half g_HB[NT];

// ---------------- CSR build ----------------
__global__ __launch_bounds__(256) void k_count(const int* __restrict__ edge) {
    int e4 = (blockIdx.x * blockDim.x + threadIdx.x) * 4;
    if (e4 < NE) {
        int4 d = *reinterpret_cast<const int4*>(edge + NE + e4);
        atomicAdd(&g_deg[d.x], 1);
        atomicAdd(&g_deg[d.y], 1);
        atomicAdd(&g_deg[d.z], 1);
        atomicAdd(&g_deg[d.w], 1);
    }
}

// exclusive scan (shuffle-based) + inv-count fused
__global__ __launch_bounds__(SCAN_B) void k_scan1() {
    __shared__ int swarp[32];
    int t    = threadIdx.x;
    int lane = t & 31;
    int wid  = t >> 5;
    int i = blockIdx.x * SCAN_B + t;
    int v = (i < NV) ? g_deg[i] : 0;
    int s = v;
#pragma unroll
    for (int off = 1; off < 32; off <<= 1) {
        int u = __shfl_up_sync(0xffffffffu, s, off);
        if (lane >= off) s += u;
    }
    if (lane == 31) swarp[wid] = s;
    __syncthreads();
    if (wid == 0) {
        int ws = swarp[lane];
        int t2 = ws;
#pragma unroll
        for (int off = 1; off < 32; off <<= 1) {
            int u = __shfl_up_sync(0xffffffffu, t2, off);
            if (lane >= off) t2 += u;
        }
        swarp[lane] = t2 - ws;   // exclusive warp offsets
    }
    __syncthreads();
    int incl = s + swarp[wid];
    if (i < NV) {
        g_rowptr[i] = incl - v;                      // block-local exclusive
        g_inv[i]    = 1.0f / (float)(v + 1);
    }
    if (t == SCAN_B - 1) g_bsum[blockIdx.x] = incl;
}

// scan3 with inlined block-sum prefix (replaces old scan2+scan3)
__global__ __launch_bounds__(256) void k_scan3() {
    __shared__ int sboff;
    int g = (blockIdx.x * 256) >> 10;        // 1024-group of this block (256 | 1024)
    if (threadIdx.x < 32) {
        int lane = threadIdx.x;
        int pre = 0, tot = 0;
#pragma unroll
        for (int base = 0; base < NBLK_SCAN; base += 32) {
            int idx = base + lane;
            int bv = (idx < NBLK_SCAN) ? g_bsum[idx] : 0;
            if (idx < g) pre += bv;
            tot += bv;
        }
#pragma unroll
        for (int off = 16; off > 0; off >>= 1) {
            pre += __shfl_down_sync(0xffffffffu, pre, off);
            tot += __shfl_down_sync(0xffffffffu, tot, off);
        }
        if (lane == 0) {
            sboff = pre;
            if (blockIdx.x == 0) g_rowptr[NV] = tot;
        }
    }
    __syncthreads();
    int i = blockIdx.x * 256 + threadIdx.x;
    if (i < NV) {
        int v = g_rowptr[i] + sboff;
        g_rowptr[i] = v;
        g_cursor[i] = v;
    }
}

__global__ __launch_bounds__(256) void k_fill(const int* __restrict__ edge) {
    int e4 = (blockIdx.x * blockDim.x + threadIdx.x) * 4;
    if (e4 < NE) {
        int4 s = *reinterpret_cast<const int4*>(edge + e4);
        int4 d = *reinterpret_cast<const int4*>(edge + NE + e4);
        g_col[atomicAdd(&g_cursor[d.x], 1)] = s.x;
        g_col[atomicAdd(&g_cursor[d.y], 1)] = s.y;
        g_col[atomicAdd(&g_cursor[d.z], 1)] = s.z;
        g_col[atomicAdd(&g_cursor[d.w], 1)] = s.w;
    }
}

// ---------------- conv1d layer 0 (cross-correlation, K=9, pad 4), x -> HA ----
__global__ __launch_bounds__(512) void k_conv(const float* __restrict__ xin,
                                              const float* __restrict__ w,
                                              const float* __restrict__ b) {
    __shared__ float sh[4][TT + 8];
    __shared__ float sw[KK];
    __shared__ float sb;
    int loc = threadIdx.x >> 7;
    int t   = threadIdx.x & 127;
    int n   = blockIdx.x * 4 + loc;
    if (threadIdx.x < KK) sw[threadIdx.x] = w[threadIdx.x];
    if (threadIdx.x == KK) sb = b[0];
    float xv = xin[n * TT + t];
    sh[loc][t + 4] = xv;
    if (t < 4)   sh[loc][t] = 0.0f;
    if (t >= TT - 4) sh[loc][t + 8] = 0.0f;
    __syncthreads();
    float y = sb;
#pragma unroll
    for (int k = 0; k < KK; k++) y += sh[loc][t + k] * sw[k];
    g_HA[n * TT + t] = __float2half(y);
}

// ---------------- fused aggregate(+mean+relu)(+conv), 2 nodes per warp ----------
__device__ __forceinline__ void acc_add8(float* acc, uint4 p) {
    __half2 h0 = *reinterpret_cast<__half2*>(&p.x);
    __half2 h1 = *reinterpret_cast<__half2*>(&p.y);
    __half2 h2 = *reinterpret_cast<__half2*>(&p.z);
    __half2 h3 = *reinterpret_cast<__half2*>(&p.w);
    float2 f0 = __half22float2(h0), f1 = __half22float2(h1);
    float2 f2 = __half22float2(h2), f3 = __half22float2(h3);
    acc[0] += f0.x; acc[1] += f0.y; acc[2] += f1.x; acc[3] += f1.y;
    acc[4] += f2.x; acc[5] += f2.y; acc[6] += f3.x; acc[7] += f3.y;
}

template <bool DO_CONV>
__global__ __launch_bounds__(256) void k_agg(const __half* __restrict__ Hin_,
                                             __half* __restrict__ Hout_,
                                             const float* __restrict__ w,
                                             const float* __restrict__ b) {
    int warp = (blockIdx.x * blockDim.x + threadIdx.x) >> 5;
    int lane = threadIdx.x & 31;
    int sub  = lane & 15;            // position within half-warp
    int n    = warp * 2 + (lane >> 4);
    if (n >= NV) return;
    const uint4* __restrict__ Hin = reinterpret_cast<const uint4*>(Hin_);

    float acc[8];
    {
        uint4 self = Hin[n * 16 + sub];
        __half2 h0 = *reinterpret_cast<__half2*>(&self.x);
        __half2 h1 = *reinterpret_cast<__half2*>(&self.y);
        __half2 h2 = *reinterpret_cast<__half2*>(&self.z);
        __half2 h3 = *reinterpret_cast<__half2*>(&self.w);
        float2 f0 = __half22float2(h0), f1 = __half22float2(h1);
        float2 f2 = __half22float2(h2), f3 = __half22float2(h3);
        acc[0] = f0.x; acc[1] = f0.y; acc[2] = f1.x; acc[3] = f1.y;
        acc[4] = f2.x; acc[5] = f2.y; acc[6] = f3.x; acc[7] = f3.y;
    }

    int e  = g_rowptr[n];
    int e1 = g_rowptr[n + 1];
    while (e < e1 && (e & 3)) {
        int s = g_col[e++];
        acc_add8(acc, Hin[s * 16 + sub]);
    }
    for (; e + 8 <= e1; e += 8) {
        int4 sa  = *reinterpret_cast<const int4*>(g_col + e);
        int4 sb2 = *reinterpret_cast<const int4*>(g_col + e + 4);
        uint4 v0 = Hin[sa.x * 16 + sub];
        uint4 v1 = Hin[sa.y * 16 + sub];
        uint4 v2 = Hin[sa.z * 16 + sub];
        uint4 v3 = Hin[sa.w * 16 + sub];
        uint4 v4 = Hin[sb2.x * 16 + sub];
        uint4 v5 = Hin[sb2.y * 16 + sub];
        uint4 v6 = Hin[sb2.z * 16 + sub];
        uint4 v7 = Hin[sb2.w * 16 + sub];
        acc_add8(acc, v0); acc_add8(acc, v1); acc_add8(acc, v2); acc_add8(acc, v3);
        acc_add8(acc, v4); acc_add8(acc, v5); acc_add8(acc, v6); acc_add8(acc, v7);
    }
    for (; e + 4 <= e1; e += 4) {
        int4 ss = *reinterpret_cast<const int4*>(g_col + e);
        uint4 v0 = Hin[ss.x * 16 + sub];
        uint4 v1 = Hin[ss.y * 16 + sub];
        uint4 v2 = Hin[ss.z * 16 + sub];
        uint4 v3 = Hin[ss.w * 16 + sub];
        acc_add8(acc, v0); acc_add8(acc, v1); acc_add8(acc, v2); acc_add8(acc, v3);
    }
    for (; e < e1; e++) {
        int s = g_col[e];
        acc_add8(acc, Hin[s * 16 + sub]);
    }

    float iv = g_inv[n];
#pragma unroll
    for (int j = 0; j < 8; j++) acc[j] = fmaxf(acc[j] * iv, 0.0f);

    float o[8];
    if (DO_CONV) {
        float win[16];
#pragma unroll
        for (int j = 0; j < 4; j++)
            win[j] = __shfl_up_sync(0xffffffffu, acc[4 + j], 1, 16);
        if (sub == 0) { win[0] = win[1] = win[2] = win[3] = 0.0f; }
#pragma unroll
        for (int j = 0; j < 8; j++) win[4 + j] = acc[j];
#pragma unroll
        for (int j = 0; j < 4; j++)
            win[12 + j] = __shfl_down_sync(0xffffffffu, acc[j], 1, 16);
        if (sub == 15) { win[12] = win[13] = win[14] = win[15] = 0.0f; }

        float wr[KK];
#pragma unroll
        for (int k = 0; k < KK; k++) wr[k] = __ldg(w + k);
        float bb = __ldg(b);
#pragma unroll
        for (int j = 0; j < 8; j++) {
            float y = bb;
#pragma unroll
            for (int k = 0; k < KK; k++) y += wr[k] * win[j + k];
            o[j] = y;
        }
    } else {
#pragma unroll
        for (int j = 0; j < 8; j++) o[j] = acc[j];
    }

    uint4 packed;
    __half2 p0 = __floats2half2_rn(o[0], o[1]);
    __half2 p1 = __floats2half2_rn(o[2], o[3]);
    __half2 p2 = __floats2half2_rn(o[4], o[5]);
    __half2 p3 = __floats2half2_rn(o[6], o[7]);
    packed.x = *reinterpret_cast<uint32_t*>(&p0);
    packed.y = *reinterpret_cast<uint32_t*>(&p1);
    packed.z = *reinterpret_cast<uint32_t*>(&p2);
    packed.w = *reinterpret_cast<uint32_t*>(&p3);
    reinterpret_cast<uint4*>(Hout_)[n * 16 + sub] = packed;
}

// ---------------- output init + flat GEMV reduce (fp16 X, flat reshape!) ------
// Reference does x.reshape(T, N) on the row-major [N,T] buffer: a RAW flat
// reinterpretation (out row r = flat[r*N : (r+1)*N]), NOT a transpose.
__global__ void k_init_out(float* __restrict__ out, const float* __restrict__ bo) {
    int i = threadIdx.x;
    if (i < TT * 3) out[i] = bo[i % 3];
}

__global__ __launch_bounds__(256) void k_reduce(const __half* __restrict__ X,
                                                const float* __restrict__ W,
                                                float* __restrict__ out) {
    long base = (long)blockIdx.x * RED_CHUNK;
    int r0 = (int)(base / NV);
    float a0 = 0, a1 = 0, a2 = 0, a3 = 0, a4 = 0, a5 = 0;
    long end = base + RED_CHUNK; if (end > (long)NT) end = NT;
    for (long i = base + 2 * threadIdx.x; i < end; i += 512) {
        __half2 h = *reinterpret_cast<const __half2*>(X + i);
        float2 f = __half22float2(h);
        unsigned r = (unsigned)(i / NV);
        unsigned c = (unsigned)(i - (long)r * NV);
        float2 w0 = *reinterpret_cast<const float2*>(W + c);
        float2 w1 = *reinterpret_cast<const float2*>(W + NV + c);
        float2 w2 = *reinterpret_cast<const float2*>(W + 2 * NV + c);
        float t0 = f.x * w0.x + f.y * w0.y;
        float t1 = f.x * w1.x + f.y * w1.y;
        float t2 = f.x * w2.x + f.y * w2.y;
        if ((int)r == r0) { a0 += t0; a1 += t1; a2 += t2; }
        else              { a3 += t0; a4 += t1; a5 += t2; }
    }
#pragma unroll
    for (int off = 16; off > 0; off >>= 1) {
        a0 += __shfl_down_sync(0xffffffffu, a0, off);
        a1 += __shfl_down_sync(0xffffffffu, a1, off);
        a2 += __shfl_down_sync(0xffffffffu, a2, off);
        a3 += __shfl_down_sync(0xffffffffu, a3, off);
        a4 += __shfl_down_sync(0xffffffffu, a4, off);
        a5 += __shfl_down_sync(0xffffffffu, a5, off);
    }
    __shared__ float s6[6];
    if (threadIdx.x < 6) s6[threadIdx.x] = 0.0f;
    __syncthreads();
    if ((threadIdx.x & 31) == 0) {
        atomicAdd(&s6[0], a0); atomicAdd(&s6[1], a1); atomicAdd(&s6[2], a2);
        atomicAdd(&s6[3], a3); atomicAdd(&s6[4], a4); atomicAdd(&s6[5], a5);
    }
    __syncthreads();
    if (threadIdx.x < 6) {
        int sel = threadIdx.x / 3;
        int j   = threadIdx.x % 3;
        int row = r0 + sel;
        if (row < TT) atomicAdd(&out[row * 3 + j], s6[threadIdx.x]);
    }
}

// ---------------- launch ----------------
extern "C" void kernel_launch(void* const* d_in, const int* in_sizes, int n_in,
                              void* d_out, int out_size) {
    const float* x      = (const float*)d_in[0];
    const int*   edge   = (const int*)d_in[1];
    const float* conv_w = (const float*)d_in[2];   // [3,1,1,9]
    const float* conv_b = (const float*)d_in[3];   // [3,1]
    const float* W_out  = (const float*)d_in[4];   // [3,NV]
    const float* b_out  = (const float*)d_in[5];   // [3]
    float* out = (float*)d_out;

    __half *HA, *HB;
    cudaGetSymbolAddress((void**)&HA, g_HA);
    cudaGetSymbolAddress((void**)&HB, g_HB);
    int* degp;
    cudaGetSymbolAddress((void**)&degp, g_deg);

    const int TB = 256;
    // CSR build
    cudaMemsetAsync(degp, 0, NV * sizeof(int));
    k_count<<<(NE / 4 + TB - 1) / TB, TB>>>(edge);
    k_scan1<<<NBLK_SCAN, SCAN_B>>>();
    k_scan3<<<(NV + 255) / 256, 256>>>();
    k_fill<<<(NE / 4 + TB - 1) / TB, TB>>>(edge);

    // layer 0 conv, then fused agg+conv, fused agg+conv, agg
    k_conv<<<NV / 4, 512>>>(x, conv_w, conv_b);
    const int AGG_GRID = (NV / 2 * 32 + TB - 1) / TB;   // 2 nodes per warp
    k_agg<true ><<<AGG_GRID, TB>>>(HA, HB, conv_w + KK,     conv_b + 1);
    k_agg<true ><<<AGG_GRID, TB>>>(HB, HA, conv_w + 2 * KK, conv_b + 2);
    k_agg<false><<<AGG_GRID, TB>>>(HA, HB, nullptr, nullptr);

    // output
    k_init_out<<<1, 384>>>(out, b_out);
    k_reduce<<<(NT + RED_CHUNK - 1) / RED_CHUNK, TB>>>(HB, W_out, out);
}

// round 9
// speedup vs baseline: 1.1076x; 1.1076x over previous
#include <cuda_runtime.h>
#include <cuda_fp16.h>
#include <cstdint>

#define NV 100000
#define TT 128
#define NE 1600000
#define KK 9
#define NT (NV * TT)
#define SCAN_B 1024
#define NBLK_SCAN ((NV + SCAN_B - 1) / SCAN_B)   // 98
#define RED_CHUNK 16384

// ---------------- scratch (static __device__, no allocation) ----------------
__device__ int    g_deg[NV];
__device__ float  g_inv[NV];
__device__ int    g_rowptr[NV + 1];
__device__ int    g_cursor[NV];
__device__ int    g_col[NE];
__device__ int    g_bsum[NBLK_SCAN];
__device__ __half g_HA[NT];
__device__ __half g_HB[NT];

// ---------------- CSR build (scalar: 1 edge/thread for atomic latency hiding) --
__global__ __launch_bounds__(256) void k_count(const int* __restrict__ edge) {
    int e = blockIdx.x * blockDim.x + threadIdx.x;
    if (e < NE) atomicAdd(&g_deg[edge[NE + e]], 1);
}

// exclusive scan (shuffle-based) + inv-count fused
__global__ __launch_bounds__(SCAN_B) void k_scan1() {
    __shared__ int swarp[32];
    int t    = threadIdx.x;
    int lane = t & 31;
    int wid  = t >> 5;
    int i = blockIdx.x * SCAN_B + t;
    int v = (i < NV) ? g_deg[i] : 0;
    int s = v;
#pragma unroll
    for (int off = 1; off < 32; off <<= 1) {
        int u = __shfl_up_sync(0xffffffffu, s, off);
        if (lane >= off) s += u;
    }
    if (lane == 31) swarp[wid] = s;
    __syncthreads();
    if (wid == 0) {
        int ws = swarp[lane];
        int t2 = ws;
#pragma unroll
        for (int off = 1; off < 32; off <<= 1) {
            int u = __shfl_up_sync(0xffffffffu, t2, off);
            if (lane >= off) t2 += u;
        }
        swarp[lane] = t2 - ws;   // exclusive warp offsets
    }
    __syncthreads();
    int incl = s + swarp[wid];
    if (i < NV) {
        g_rowptr[i] = incl - v;                      // block-local exclusive
        g_inv[i]    = 1.0f / (float)(v + 1);
    }
    if (t == SCAN_B - 1) g_bsum[blockIdx.x] = incl;
}

// scan3 with inlined block-sum prefix (replaces separate scan2 kernel)
__global__ __launch_bounds__(256) void k_scan3() {
    __shared__ int sboff;
    int g = (blockIdx.x * 256) >> 10;        // 1024-group of this block (256 | 1024)
    if (threadIdx.x < 32) {
        int lane = threadIdx.x;
        int pre = 0, tot = 0;
#pragma unroll
        for (int base = 0; base < NBLK_SCAN; base += 32) {
            int idx = base + lane;
            int bv = (idx < NBLK_SCAN) ? g_bsum[idx] : 0;
            if (idx < g) pre += bv;
            tot += bv;
        }
#pragma unroll
        for (int off = 16; off > 0; off >>= 1) {
            pre += __shfl_down_sync(0xffffffffu, pre, off);
            tot += __shfl_down_sync(0xffffffffu, tot, off);
        }
        if (lane == 0) {
            sboff = pre;
            if (blockIdx.x == 0) g_rowptr[NV] = tot;
        }
    }
    __syncthreads();
    int i = blockIdx.x * 256 + threadIdx.x;
    if (i < NV) {
        int v = g_rowptr[i] + sboff;
        g_rowptr[i] = v;
        g_cursor[i] = v;
    }
}

__global__ __launch_bounds__(256) void k_fill(const int* __restrict__ edge) {
    int e = blockIdx.x * blockDim.x + threadIdx.x;
    if (e < NE) {
        int s = edge[e];
        int d = edge[NE + e];
        int p = atomicAdd(&g_cursor[d], 1);
        g_col[p] = s;
    }
}

// ---------------- conv1d layer 0 (cross-correlation, K=9, pad 4), x -> HA ----
__global__ __launch_bounds__(512) void k_conv(const float* __restrict__ xin,
                                              const float* __restrict__ w,
                                              const float* __restrict__ b) {
    __shared__ float sh[4][TT + 8];
    __shared__ float sw[KK];
    __shared__ float sb;
    int loc = threadIdx.x >> 7;
    int t   = threadIdx.x & 127;
    int n   = blockIdx.x * 4 + loc;
    if (threadIdx.x < KK) sw[threadIdx.x] = w[threadIdx.x];
    if (threadIdx.x == KK) sb = b[0];
    float xv = xin[n * TT + t];
    sh[loc][t + 4] = xv;
    if (t < 4)   sh[loc][t] = 0.0f;
    if (t >= TT - 4) sh[loc][t + 8] = 0.0f;
    __syncthreads();
    float y = sb;
#pragma unroll
    for (int k = 0; k < KK; k++) y += sh[loc][t + k] * sw[k];
    g_HA[n * TT + t] = __float2half(y);
}

// ---------------- fused aggregate(+mean+relu)(+conv), 2 nodes per warp ----------
// lanes 0-15 own node 2w, lanes 16-31 own node 2w+1; each lane holds 8 halves (uint4).
__device__ __forceinline__ void acc_add8(float* acc, uint4 p) {
    __half2 h0 = *reinterpret_cast<__half2*>(&p.x);
    __half2 h1 = *reinterpret_cast<__half2*>(&p.y);
    __half2 h2 = *reinterpret_cast<__half2*>(&p.z);
    __half2 h3 = *reinterpret_cast<__half2*>(&p.w);
    float2 f0 = __half22float2(h0), f1 = __half22float2(h1);
    float2 f2 = __half22float2(h2), f3 = __half22float2(h3);
    acc[0] += f0.x; acc[1] += f0.y; acc[2] += f1.x; acc[3] += f1.y;
    acc[4] += f2.x; acc[5] += f2.y; acc[6] += f3.x; acc[7] += f3.y;
}

template <bool DO_CONV>
__global__ __launch_bounds__(256) void k_agg(const __half* __restrict__ Hin_,
                                             __half* __restrict__ Hout_,
                                             const float* __restrict__ w,
                                             const float* __restrict__ b) {
    int warp = (blockIdx.x * blockDim.x + threadIdx.x) >> 5;
    int lane = threadIdx.x & 31;
    int sub  = lane & 15;            // position within half-warp
    int n    = warp * 2 + (lane >> 4);
    if (n >= NV) return;
    const uint4* __restrict__ Hin = reinterpret_cast<const uint4*>(Hin_);

    float acc[8];
    {
        uint4 self = Hin[n * 16 + sub];
        __half2 h0 = *reinterpret_cast<__half2*>(&self.x);
        __half2 h1 = *reinterpret_cast<__half2*>(&self.y);
        __half2 h2 = *reinterpret_cast<__half2*>(&self.z);
        __half2 h3 = *reinterpret_cast<__half2*>(&self.w);
        float2 f0 = __half22float2(h0), f1 = __half22float2(h1);
        float2 f2 = __half22float2(h2), f3 = __half22float2(h3);
        acc[0] = f0.x; acc[1] = f0.y; acc[2] = f1.x; acc[3] = f1.y;
        acc[4] = f2.x; acc[5] = f2.y; acc[6] = f3.x; acc[7] = f3.y;
    }

    int e  = g_rowptr[n];
    int e1 = g_rowptr[n + 1];
    while (e < e1 && (e & 3)) {
        int s = g_col[e++];
        acc_add8(acc, Hin[s * 16 + sub]);
    }
    for (; e + 4 <= e1; e += 4) {
        int4 ss = *reinterpret_cast<const int4*>(g_col + e);
        uint4 v0 = Hin[ss.x * 16 + sub];
        uint4 v1 = Hin[ss.y * 16 + sub];
        uint4 v2 = Hin[ss.z * 16 + sub];
        uint4 v3 = Hin[ss.w * 16 + sub];
        acc_add8(acc, v0); acc_add8(acc, v1); acc_add8(acc, v2); acc_add8(acc, v3);
    }
    for (; e < e1; e++) {
        int s = g_col[e];
        acc_add8(acc, Hin[s * 16 + sub]);
    }

    float iv = g_inv[n];
#pragma unroll
    for (int j = 0; j < 8; j++) acc[j] = fmaxf(acc[j] * iv, 0.0f);

    float o[8];
    if (DO_CONV) {
        // window win[0..15]: win[0..3] = prev lane's acc[4..7], win[4..11] = own,
        // win[12..15] = next lane's acc[0..3]; zero at t<0 / t>=TT.
        float win[16];
#pragma unroll
        for (int j = 0; j < 4; j++)
            win[j] = __shfl_up_sync(0xffffffffu, acc[4 + j], 1, 16);
        if (sub == 0) { win[0] = win[1] = win[2] = win[3] = 0.0f; }
#pragma unroll
        for (int j = 0; j < 8; j++) win[4 + j] = acc[j];
#pragma unroll
        for (int j = 0; j < 4; j++)
            win[12 + j] = __shfl_down_sync(0xffffffffu, acc[j], 1, 16);
        if (sub == 15) { win[12] = win[13] = win[14] = win[15] = 0.0f; }

        float wr[KK];
#pragma unroll
        for (int k = 0; k < KK; k++) wr[k] = __ldg(w + k);
        float bb = __ldg(b);
#pragma unroll
        for (int j = 0; j < 8; j++) {
            float y = bb;
#pragma unroll
            for (int k = 0; k < KK; k++) y += wr[k] * win[j + k];
            o[j] = y;
        }
    } else {
#pragma unroll
        for (int j = 0; j < 8; j++) o[j] = acc[j];
    }

    uint4 packed;
    __half2 p0 = __floats2half2_rn(o[0], o[1]);
    __half2 p1 = __floats2half2_rn(o[2], o[3]);
    __half2 p2 = __floats2half2_rn(o[4], o[5]);
    __half2 p3 = __floats2half2_rn(o[6], o[7]);
    packed.x = *reinterpret_cast<uint32_t*>(&p0);
    packed.y = *reinterpret_cast<uint32_t*>(&p1);
    packed.z = *reinterpret_cast<uint32_t*>(&p2);
    packed.w = *reinterpret_cast<uint32_t*>(&p3);
    reinterpret_cast<uint4*>(Hout_)[n * 16 + sub] = packed;
}

// ---------------- output init + flat GEMV reduce (fp16 X, RAW flat reshape) ----
// Reference does x.reshape(T, N) on the row-major [N,T] buffer: a flat
// reinterpretation (out row r = flat[r*N : (r+1)*N]), NOT a transpose.
__global__ void k_init_out(float* __restrict__ out, const float* __restrict__ bo) {
    int i = threadIdx.x;
    if (i < TT * 3) out[i] = bo[i % 3];
}

__global__ __launch_bounds__(256) void k_reduce(const __half* __restrict__ X,
                                                const float* __restrict__ W,
                                                float* __restrict__ out) {
    long base = (long)blockIdx.x * RED_CHUNK;
    int r0 = (int)(base / NV);
    float a0 = 0, a1 = 0, a2 = 0, a3 = 0, a4 = 0, a5 = 0;
    long end = base + RED_CHUNK; if (end > (long)NT) end = NT;
    for (long i = base + 2 * threadIdx.x; i < end; i += 512) {
        __half2 h = *reinterpret_cast<const __half2*>(X + i);
        float2 f = __half22float2(h);
        unsigned r = (unsigned)(i / NV);
        unsigned c = (unsigned)(i - (long)r * NV);
        float2 w0 = *reinterpret_cast<const float2*>(W + c);
        float2 w1 = *reinterpret_cast<const float2*>(W + NV + c);
        float2 w2 = *reinterpret_cast<const float2*>(W + 2 * NV + c);
        float t0 = f.x * w0.x + f.y * w0.y;
        float t1 = f.x * w1.x + f.y * w1.y;
        float t2 = f.x * w2.x + f.y * w2.y;
        if ((int)r == r0) { a0 += t0; a1 += t1; a2 += t2; }
        else              { a3 += t0; a4 += t1; a5 += t2; }
    }
#pragma unroll
    for (int off = 16; off > 0; off >>= 1) {
        a0 += __shfl_down_sync(0xffffffffu, a0, off);
        a1 += __shfl_down_sync(0xffffffffu, a1, off);
        a2 += __shfl_down_sync(0xffffffffu, a2, off);
        a3 += __shfl_down_sync(0xffffffffu, a3, off);
        a4 += __shfl_down_sync(0xffffffffu, a4, off);
        a5 += __shfl_down_sync(0xffffffffu, a5, off);
    }
    __shared__ float s6[6];
    if (threadIdx.x < 6) s6[threadIdx.x] = 0.0f;
    __syncthreads();
    if ((threadIdx.x & 31) == 0) {
        atomicAdd(&s6[0], a0); atomicAdd(&s6[1], a1); atomicAdd(&s6[2], a2);
        atomicAdd(&s6[3], a3); atomicAdd(&s6[4], a4); atomicAdd(&s6[5], a5);
    }
    __syncthreads();
    if (threadIdx.x < 6) {
        int sel = threadIdx.x / 3;
        int j   = threadIdx.x % 3;
        int row = r0 + sel;
        if (row < TT) atomicAdd(&out[row * 3 + j], s6[threadIdx.x]);
    }
}

// ---------------- launch ----------------
extern "C" void kernel_launch(void* const* d_in, const int* in_sizes, int n_in,
                              void* d_out, int out_size) {
    const float* x      = (const float*)d_in[0];
    const int*   edge   = (const int*)d_in[1];
    const float* conv_w = (const float*)d_in[2];   // [3,1,1,9]
    const float* conv_b = (const float*)d_in[3];   // [3,1]
    const float* W_out  = (const float*)d_in[4];   // [3,NV]
    const float* b_out  = (const float*)d_in[5];   // [3]
    float* out = (float*)d_out;

    __half *HA, *HB;
    cudaGetSymbolAddress((void**)&HA, g_HA);
    cudaGetSymbolAddress((void**)&HB, g_HB);
    int* degp;
    cudaGetSymbolAddress((void**)&degp, g_deg);

    const int TB = 256;
    // CSR build
    cudaMemsetAsync(degp, 0, NV * sizeof(int));
    k_count<<<(NE + TB - 1) / TB, TB>>>(edge);
    k_scan1<<<NBLK_SCAN, SCAN_B>>>();
    k_scan3<<<(NV + 255) / 256, 256>>>();
    k_fill<<<(NE + TB - 1) / TB, TB>>>(edge);

    // layer 0 conv, then fused agg+conv, fused agg+conv, agg
    k_conv<<<NV / 4, 512>>>(x, conv_w, conv_b);
    const int AGG_GRID = (NV / 2 * 32 + TB - 1) / TB;   // 2 nodes per warp
    k_agg<true ><<<AGG_GRID, TB>>>(HA, HB, conv_w + KK,     conv_b + 1);
    k_agg<true ><<<AGG_GRID, TB>>>(HB, HA, conv_w + 2 * KK, conv_b + 2);
    k_agg<false><<<AGG_GRID, TB>>>(HA, HB, nullptr, nullptr);

    // output
    k_init_out<<<1, 384>>>(out, b_out);
    k_reduce<<<(NT + RED_CHUNK - 1) / RED_CHUNK, TB>>>(HB, W_out, out);
}